// round 3
// baseline (speedup 1.0000x reference)
#include <cuda_runtime.h>
#include <cuda_bf16.h>

// Contour_to_mask: winding-number mask, 512x512 pixels x 128 contour points.
// out = clamp( sum_n tanh(K*cross_n) * acos(clamp(cos_n,-1+eps,1-eps)) / (2pi), 0, 1 )
// 4 pixels/thread (same row), packed f32x2 arithmetic for the lane-parallel math,
// polynomial acos (sqrt(1-|x|)*P(|x|)), HW tanh.approx, carried diff.

#define MSIZE 512
#define NPTS  128
#define KCONST 100000.0f
#define EPSC   1e-5f
#define INV2PI 0.15915494309189535f
#define PI_F   3.14159265358979323846f

typedef unsigned long long u64;

__device__ __forceinline__ u64 pk2(float lo, float hi) {
    u64 r; asm("mov.b64 %0,{%1,%2};" : "=l"(r) : "f"(lo), "f"(hi)); return r;
}
__device__ __forceinline__ void upk2(u64 v, float& lo, float& hi) {
    asm("mov.b64 {%0,%1},%2;" : "=f"(lo), "=f"(hi) : "l"(v));
}
__device__ __forceinline__ u64 mul2(u64 a, u64 b) {
    u64 r; asm("mul.rn.f32x2 %0,%1,%2;" : "=l"(r) : "l"(a), "l"(b)); return r;
}
__device__ __forceinline__ u64 add2(u64 a, u64 b) {
    u64 r; asm("add.rn.f32x2 %0,%1,%2;" : "=l"(r) : "l"(a), "l"(b)); return r;
}
__device__ __forceinline__ u64 fma2(u64 a, u64 b, u64 c) {
    u64 r; asm("fma.rn.f32x2 %0,%1,%2,%3;" : "=l"(r) : "l"(a), "l"(b), "l"(c)); return r;
}
__device__ __forceinline__ float ftanh(float x) {
    float r; asm("tanh.approx.f32 %0,%1;" : "=f"(r) : "f"(x)); return r;
}

__global__ void __launch_bounds__(128)
contour_mask_kernel(const float* __restrict__ contour, float* __restrict__ out) {
    __shared__ float2 c[NPTS];
    const int t = threadIdx.x;
    if (t < NPTS) c[t] = reinterpret_cast<const float2*>(contour)[t];
    __syncthreads();

    const int row = blockIdx.x;
    const float px = (float)row * (1.0f / (float)MSIZE);

    // 4 pixels: columns t, t+128 (pair A) and t+256, t+384 (pair B)
    const u64 npyA = pk2(-(float)t         * (1.0f / MSIZE),
                         -(float)(t + 128) * (1.0f / MSIZE));
    const u64 npyB = pk2(-(float)(t + 256) * (1.0f / MSIZE),
                         -(float)(t + 384) * (1.0f / MSIZE));

    // acos poly coefficients (acos(ax) ~= sqrt(1-ax)*P(ax)), packed
    const u64 C7 = pk2(-0.0012624911f, -0.0012624911f);
    const u64 C6 = pk2( 0.0066700901f,  0.0066700901f);
    const u64 C5 = pk2(-0.0170881256f, -0.0170881256f);
    const u64 C4 = pk2( 0.0308918810f,  0.0308918810f);
    const u64 C3 = pk2(-0.0501743046f, -0.0501743046f);
    const u64 C2 = pk2( 0.0889789874f,  0.0889789874f);
    const u64 C1 = pk2(-0.2145988016f, -0.2145988016f);
    const u64 C0 = pk2( 1.5707963050f,  1.5707963050f);

    // carried diff for edge start 0 (roll of edge j == diff of edge j+1)
    float dx = c[0].x - px;
    {
        // init handled below via packed state
    }
    u64 cy0v = pk2(c[0].y, c[0].y);
    u64 dyA = add2(cy0v, npyA);
    u64 dyB = add2(cy0v, npyB);
    u64 dxxv = pk2(dx * dx, dx * dx);
    u64 d2A = fma2(dyA, dyA, dxxv);
    u64 d2B = fma2(dyB, dyB, dxxv);

    float sum0 = 0.0f, sum1 = 0.0f, sum2 = 0.0f, sum3 = 0.0f;

#pragma unroll 4
    for (int j = 0; j < NPTS; ++j) {
        const float2 cn = c[(j + 1) & (NPTS - 1)];
        const float rx   = cn.x - px;
        const float ndx  = -dx;
        const float dxrx = dx * rx;
        const u64 rxv   = pk2(rx, rx);
        const u64 cnyv  = pk2(cn.y, cn.y);
        const u64 ndxv  = pk2(ndx, ndx);
        const u64 dxrxv = pk2(dxrx, dxrx);
        const u64 rxxv  = mul2(rxv, rxv);

        // ---- packed front-end, pair A ----
        const u64 ryA = add2(cnyv, npyA);
        const u64 r2A = fma2(ryA, ryA, rxxv);
        const u64 crA = fma2(dyA, rxv, mul2(ndxv, ryA));   // dy*rx - dx*ry
        const u64 dtA = fma2(dyA, ryA, dxrxv);             // dy*ry + dx*rx
        const u64 m2A = mul2(d2A, r2A);
        // ---- packed front-end, pair B ----
        const u64 ryB = add2(cnyv, npyB);
        const u64 r2B = fma2(ryB, ryB, rxxv);
        const u64 crB = fma2(dyB, rxv, mul2(ndxv, ryB));
        const u64 dtB = fma2(dyB, ryB, dxrxv);
        const u64 m2B = mul2(d2B, r2B);

        float m0, m1, m2_, m3, do0, do1, do2, do3, cr0, cr1, cr2, cr3;
        upk2(m2A, m0, m1);   upk2(m2B, m2_, m3);
        upk2(dtA, do0, do1); upk2(dtB, do2, do3);
        upk2(crA, cr0, cr1); upk2(crB, cr2, cr3);

        const float inv0 = rsqrtf(m0), inv1 = rsqrtf(m1);
        const float inv2 = rsqrtf(m2_), inv3 = rsqrtf(m3);
        const float cos0 = do0 * inv0, cos1 = do1 * inv1;
        const float cos2 = do2 * inv2, cos3 = do3 * inv3;

        // t = max(1-|cos|, eps)  == both reference clamps folded
        const float t0 = fmaxf(1.0f - fabsf(cos0), EPSC);
        const float t1 = fmaxf(1.0f - fabsf(cos1), EPSC);
        const float t2 = fmaxf(1.0f - fabsf(cos2), EPSC);
        const float t3 = fmaxf(1.0f - fabsf(cos3), EPSC);
        const float s0 = t0 * rsqrtf(t0);   // sqrt(t)
        const float s1 = t1 * rsqrtf(t1);
        const float s2 = t2 * rsqrtf(t2);
        const float s3 = t3 * rsqrtf(t3);

        // packed 7-FMA acos polynomial on ax = |cos|
        const u64 axA = pk2(fabsf(cos0), fabsf(cos1));
        const u64 axB = pk2(fabsf(cos2), fabsf(cos3));
        u64 pA = fma2(C7, axA, C6);
        u64 pB = fma2(C7, axB, C6);
        pA = fma2(pA, axA, C5);  pB = fma2(pB, axB, C5);
        pA = fma2(pA, axA, C4);  pB = fma2(pB, axB, C4);
        pA = fma2(pA, axA, C3);  pB = fma2(pB, axB, C3);
        pA = fma2(pA, axA, C2);  pB = fma2(pB, axB, C2);
        pA = fma2(pA, axA, C1);  pB = fma2(pB, axB, C1);
        pA = fma2(pA, axA, C0);  pB = fma2(pB, axB, C0);

        float p0, p1, p2, p3;
        upk2(pA, p0, p1); upk2(pB, p2, p3);

        const float r0 = s0 * p0, r1 = s1 * p1, r2 = s2 * p2, r3 = s3 * p3;
        const float ang0 = (do0 < 0.0f) ? (PI_F - r0) : r0;
        const float ang1 = (do1 < 0.0f) ? (PI_F - r1) : r1;
        const float ang2 = (do2 < 0.0f) ? (PI_F - r2) : r2;
        const float ang3 = (do3 < 0.0f) ? (PI_F - r3) : r3;

        const float th0 = ftanh(KCONST * cr0);
        const float th1 = ftanh(KCONST * cr1);
        const float th2 = ftanh(KCONST * cr2);
        const float th3 = ftanh(KCONST * cr3);

        sum0 = fmaf(th0, ang0, sum0);
        sum1 = fmaf(th1, ang1, sum1);
        sum2 = fmaf(th2, ang2, sum2);
        sum3 = fmaf(th3, ang3, sum3);

        // carry: this edge's roll is next edge's diff
        dx = rx;
        dyA = ryA; dyB = ryB;
        d2A = r2A; d2B = r2B;
    }

    const int base = row * MSIZE + t;
    out[base]       = fminf(fmaxf(sum0 * INV2PI, 0.0f), 1.0f);
    out[base + 128] = fminf(fmaxf(sum1 * INV2PI, 0.0f), 1.0f);
    out[base + 256] = fminf(fmaxf(sum2 * INV2PI, 0.0f), 1.0f);
    out[base + 384] = fminf(fmaxf(sum3 * INV2PI, 0.0f), 1.0f);
}

extern "C" void kernel_launch(void* const* d_in, const int* in_sizes, int n_in,
                              void* d_out, int out_size) {
    const float* contour = (const float*)d_in[0];
    float* out = (float*)d_out;
    contour_mask_kernel<<<MSIZE, 128>>>(contour, out);
}

// round 4
// speedup vs baseline: 1.0148x; 1.0148x over previous
#include <cuda_runtime.h>
#include <cuda_bf16.h>

// Contour_to_mask: winding-number mask, 512x512 pixels x 128 contour points.
// out = clamp( sum_n tanh(K*cross_n) * acos(clamp(cos_n,-1+eps,1-eps)) / (2pi), 0, 1 )
// 2 pixels/thread packed in f32x2 end-to-end (contour stored duplicated in smem
// so no pack movs), polynomial acos, HW tanh.approx, carried diff
// (roll_j == diff_{j+1}), grid sized for occupancy/balance (1024 blocks x 128).

#define MSIZE 512
#define NPTS  128
#define KCONST 100000.0f
#define EPSC   1e-5f
#define INV2PI 0.15915494309189535f
#define PI_F   3.14159265358979323846f

typedef unsigned long long u64;

__device__ __forceinline__ u64 pk2(float lo, float hi) {
    u64 r; asm("mov.b64 %0,{%1,%2};" : "=l"(r) : "f"(lo), "f"(hi)); return r;
}
__device__ __forceinline__ void upk2(u64 v, float& lo, float& hi) {
    asm("mov.b64 {%0,%1},%2;" : "=f"(lo), "=f"(hi) : "l"(v));
}
__device__ __forceinline__ u64 mul2(u64 a, u64 b) {
    u64 r; asm("mul.rn.f32x2 %0,%1,%2;" : "=l"(r) : "l"(a), "l"(b)); return r;
}
__device__ __forceinline__ u64 add2(u64 a, u64 b) {
    u64 r; asm("add.rn.f32x2 %0,%1,%2;" : "=l"(r) : "l"(a), "l"(b)); return r;
}
__device__ __forceinline__ u64 fma2(u64 a, u64 b, u64 c) {
    u64 r; asm("fma.rn.f32x2 %0,%1,%2,%3;" : "=l"(r) : "l"(a), "l"(b), "l"(c)); return r;
}
__device__ __forceinline__ u64 neg2(u64 a) {            // flip both sign bits (LOP3, alu pipe)
    return a ^ 0x8000000080000000ULL;
}
__device__ __forceinline__ float ftanh(float x) {
    float r; asm("tanh.approx.f32 %0,%1;" : "=f"(r) : "f"(x)); return r;
}

__global__ void __launch_bounds__(128)
contour_mask_kernel(const float* __restrict__ contour, float* __restrict__ out) {
    // contour duplicated into lane-pair form: cxd[j] = (cx,cx), cyd[j] = (cy,cy)
    __shared__ float2 cxd[NPTS];
    __shared__ float2 cyd[NPTS];
    const int t = threadIdx.x;
    if (t < NPTS) {
        const float2 p = reinterpret_cast<const float2*>(contour)[t];
        cxd[t] = make_float2(p.x, p.x);
        cyd[t] = make_float2(p.y, p.y);
    }
    __syncthreads();

    // 1024 blocks: row = bx>>1, half-row = bx&1. Pixels: (row, col) and (row, col+128).
    const int row  = blockIdx.x >> 1;
    const int col0 = ((blockIdx.x & 1) << 8) + t;     // 0..255 or 256..511
    const float px  = (float)row * (1.0f / (float)MSIZE);
    const u64 npxv = pk2(-px, -px);
    const u64 npyv = pk2(-(float)col0        * (1.0f / MSIZE),
                         -(float)(col0 + 128) * (1.0f / MSIZE));

    // acos poly coefficients (acos(ax) ~= sqrt(1-ax)*P(ax)), packed
    const u64 C7 = pk2(-0.0012624911f, -0.0012624911f);
    const u64 C6 = pk2( 0.0066700901f,  0.0066700901f);
    const u64 C5 = pk2(-0.0170881256f, -0.0170881256f);
    const u64 C4 = pk2( 0.0308918810f,  0.0308918810f);
    const u64 C3 = pk2(-0.0501743046f, -0.0501743046f);
    const u64 C2 = pk2( 0.0889789874f,  0.0889789874f);
    const u64 C1 = pk2(-0.2145988016f, -0.2145988016f);
    const u64 C0 = pk2( 1.5707963050f,  1.5707963050f);
    const u64 NEG1 = pk2(-1.0f, -1.0f);
    const u64 ONE  = pk2( 1.0f,  1.0f);

    const u64* cxv = reinterpret_cast<const u64*>(cxd);
    const u64* cyv = reinterpret_cast<const u64*>(cyd);

    // carried diff for edge start 0 (roll of edge j == diff of edge j+1)
    u64 dxv = add2(cxv[0], npxv);
    u64 dyv = add2(cyv[0], npyv);
    u64 d2v = fma2(dyv, dyv, mul2(dxv, dxv));

    float sum0 = 0.0f, sum1 = 0.0f;

#pragma unroll 8
    for (int j = 0; j < NPTS; ++j) {
        const int jn = (j + 1) & (NPTS - 1);
        const u64 rxv = add2(cxv[jn], npxv);
        const u64 ryv = add2(cyv[jn], npyv);

        const u64 r2v = fma2(ryv, ryv, mul2(rxv, rxv));
        const u64 crv = fma2(dyv, rxv, neg2(mul2(dxv, ryv)));  // dy*rx - dx*ry
        const u64 dtv = fma2(dyv, ryv, mul2(dxv, rxv));        // dot
        const u64 m2v = mul2(d2v, r2v);

        float m0, m1, do0, do1, cr0, cr1;
        upk2(m2v, m0, m1);
        upk2(dtv, do0, do1);
        upk2(crv, cr0, cr1);

        const float cos0 = do0 * rsqrtf(m0);
        const float cos1 = do1 * rsqrtf(m1);
        const float ax0 = fabsf(cos0), ax1 = fabsf(cos1);

        // t = max(1-|cos|, eps): packed 1-ax, scalar fmax
        const u64 axv = pk2(ax0, ax1);
        float u0, u1;
        upk2(fma2(axv, NEG1, ONE), u0, u1);
        const float t0 = fmaxf(u0, EPSC);
        const float t1 = fmaxf(u1, EPSC);
        const float s0 = t0 * rsqrtf(t0);   // sqrt(t)
        const float s1 = t1 * rsqrtf(t1);

        // packed 7-FMA acos polynomial on ax
        u64 pv = fma2(C7, axv, C6);
        pv = fma2(pv, axv, C5);
        pv = fma2(pv, axv, C4);
        pv = fma2(pv, axv, C3);
        pv = fma2(pv, axv, C2);
        pv = fma2(pv, axv, C1);
        pv = fma2(pv, axv, C0);
        float p0, p1;
        upk2(pv, p0, p1);

        const float r0 = s0 * p0, r1 = s1 * p1;
        const float ang0 = (cos0 < 0.0f) ? (PI_F - r0) : r0;
        const float ang1 = (cos1 < 0.0f) ? (PI_F - r1) : r1;

        const float th0 = ftanh(KCONST * cr0);
        const float th1 = ftanh(KCONST * cr1);

        sum0 = fmaf(th0, ang0, sum0);
        sum1 = fmaf(th1, ang1, sum1);

        // carry: this edge's roll is next edge's diff
        dxv = rxv; dyv = ryv; d2v = r2v;
    }

    const int base = row * MSIZE + col0;
    out[base]       = fminf(fmaxf(sum0 * INV2PI, 0.0f), 1.0f);
    out[base + 128] = fminf(fmaxf(sum1 * INV2PI, 0.0f), 1.0f);
}

extern "C" void kernel_launch(void* const* d_in, const int* in_sizes, int n_in,
                              void* d_out, int out_size) {
    const float* contour = (const float*)d_in[0];
    float* out = (float*)d_out;
    contour_mask_kernel<<<MSIZE * 2, 128>>>(contour, out);
}

// round 5
// speedup vs baseline: 1.0491x; 1.0338x over previous
#include <cuda_runtime.h>
#include <cuda_bf16.h>

// Contour_to_mask: winding-number mask, 512x512 pixels x 128 contour points.
// Reference: sum_n tanh(K*cross_n) * acos(clip(dot_n/(|d||r|), -1+eps, 1-eps)) / 2pi, clipped [0,1].
// Key identity: theta = acos(dot/(|d||r|)) = atan2(|cross|, dot)  (since |cross| = |d||r| sin,
// dot = |d||r| cos, sin >= 0). The reference clamp maps EXACTLY to clamping theta to
// [acos(1-eps), pi - acos(1-eps)] because acos is monotone. This removes both rsqrt ops
// (no norms needed at all) -> 2 MUFU/px (RCP + TANH) instead of 3.
// 2 px/thread packed f32x2, contour in smem as (cx,cx,cy,cy) for one LDS.128/iter,
// carried diff (roll_j == diff_{j+1}).

#define MSIZE 512
#define NPTS  128
#define KCONST 100000.0f
#define INV2PI 0.15915494309189535f
#define PI_F   3.14159265358979323846f
#define PI_2F  1.57079632679489662f
#define THMIN  0.0044721364f            /* acos(1 - 1e-5) */
#define THMAX  3.1371205172f            /* pi - acos(1 - 1e-5) */

typedef unsigned long long u64;

__device__ __forceinline__ u64 pk2(float lo, float hi) {
    u64 r; asm("mov.b64 %0,{%1,%2};" : "=l"(r) : "f"(lo), "f"(hi)); return r;
}
__device__ __forceinline__ void upk2(u64 v, float& lo, float& hi) {
    asm("mov.b64 {%0,%1},%2;" : "=f"(lo), "=f"(hi) : "l"(v));
}
__device__ __forceinline__ u64 mul2(u64 a, u64 b) {
    u64 r; asm("mul.rn.f32x2 %0,%1,%2;" : "=l"(r) : "l"(a), "l"(b)); return r;
}
__device__ __forceinline__ u64 add2(u64 a, u64 b) {
    u64 r; asm("add.rn.f32x2 %0,%1,%2;" : "=l"(r) : "l"(a), "l"(b)); return r;
}
__device__ __forceinline__ u64 fma2(u64 a, u64 b, u64 c) {
    u64 r; asm("fma.rn.f32x2 %0,%1,%2,%3;" : "=l"(r) : "l"(a), "l"(b), "l"(c)); return r;
}
__device__ __forceinline__ u64 neg2(u64 a) { return a ^ 0x8000000080000000ULL; }
__device__ __forceinline__ float ftanh(float x) {
    float r; asm("tanh.approx.f32 %0,%1;" : "=f"(r) : "f"(x)); return r;
}
__device__ __forceinline__ float frcp(float x) {
    float r; asm("rcp.approx.f32 %0,%1;" : "=f"(r) : "f"(x)); return r;
}

__global__ void __launch_bounds__(128)
contour_mask_kernel(const float* __restrict__ contour, float* __restrict__ out) {
    // contour as (cx,cx,cy,cy) -> one LDS.128 per edge
    __shared__ float4 c4[NPTS];
    const int t = threadIdx.x;
    if (t < NPTS) {
        const float2 p = reinterpret_cast<const float2*>(contour)[t];
        c4[t] = make_float4(p.x, p.x, p.y, p.y);
    }
    __syncthreads();

    const int row  = blockIdx.x >> 1;
    const int col0 = ((blockIdx.x & 1) << 8) + t;
    const float px = (float)row * (1.0f / (float)MSIZE);
    const u64 npxv = pk2(-px, -px);
    const u64 npyv = pk2(-(float)col0         * (1.0f / MSIZE),
                         -(float)(col0 + 128) * (1.0f / MSIZE));

    // atan poly (A&S 4.4.49, |err| <= 2e-8 on [0,1]), packed coefficients
    const u64 A15 = pk2(-0.0040540580f, -0.0040540580f);
    const u64 A13 = pk2( 0.0218612288f,  0.0218612288f);
    const u64 A11 = pk2(-0.0559098861f, -0.0559098861f);
    const u64 A9  = pk2( 0.0964200441f,  0.0964200441f);
    const u64 A7  = pk2(-0.1390853351f, -0.1390853351f);
    const u64 A5  = pk2( 0.1994653599f,  0.1994653599f);
    const u64 A3  = pk2(-0.3332985605f, -0.3332985605f);
    const u64 A1  = pk2( 0.9999993329f,  0.9999993329f);
    const u64 KV  = pk2(KCONST, KCONST);

    const u64* cv = reinterpret_cast<const u64*>(c4);  // cv[2j]=(cx,cx), cv[2j+1]=(cy,cy)

    // carried diff for edge start 0 (roll of edge j == diff of edge j+1)
    u64 dxv = add2(cv[0], npxv);
    u64 dyv = add2(cv[1], npyv);

    float sum0 = 0.0f, sum1 = 0.0f;

#pragma unroll 8
    for (int j = 0; j < NPTS; ++j) {
        const int jn = (j + 1) & (NPTS - 1);
        const u64 rxv = add2(cv[2 * jn], npxv);
        const u64 ryv = add2(cv[2 * jn + 1], npyv);

        const u64 crv = fma2(dyv, rxv, neg2(mul2(dxv, ryv)));  // dy*rx - dx*ry
        const u64 dtv = fma2(dxv, rxv, mul2(dyv, ryv));        // dx*rx + dy*ry
        const u64 tkv = mul2(crv, KV);                         // K*cross (packed)

        float cr0, cr1, c0, c1, tk0, tk1;
        upk2(crv, cr0, cr1);
        upk2(dtv, c0, c1);
        upk2(tkv, tk0, tk1);

        // range-reduce: r = min(|cr|,|c|)/max(|cr|,|c|) in [0,1]
        const float a0 = fabsf(cr0), a1 = fabsf(cr1);
        const float b0 = fabsf(c0),  b1 = fabsf(c1);
        const float M0 = fmaxf(a0, b0), M1 = fmaxf(a1, b1);
        const float m0 = fminf(a0, b0), m1 = fminf(a1, b1);
        const float r0 = m0 * frcp(M0);
        const float r1 = m1 * frcp(M1);

        // packed odd poly: alpha = r * P(r^2), alpha = atan(r) in [0, pi/4]
        const u64 rv  = pk2(r0, r1);
        const u64 r2v = mul2(rv, rv);
        u64 pv = fma2(A15, r2v, A13);
        pv = fma2(pv, r2v, A11);
        pv = fma2(pv, r2v, A9);
        pv = fma2(pv, r2v, A7);
        pv = fma2(pv, r2v, A5);
        pv = fma2(pv, r2v, A3);
        pv = fma2(pv, r2v, A1);
        const u64 av = mul2(pv, rv);
        float al0, al1;
        upk2(av, al0, al1);

        // quadrant fixup: p = |cr|>|c| (alpha measured from the dot axis or cross axis)
        //  (!p,c>=0): th=a      (!p,c<0): th=pi-a
        //  ( p,c>=0): th=pi/2-a ( p,c<0): th=pi/2+a
        const bool p0 = a0 > b0, p1 = a1 > b1;
        const bool n0 = c0 < 0.0f, n1 = c1 < 0.0f;
        const float base0 = p0 ? PI_2F : (n0 ? PI_F : 0.0f);
        const float base1 = p1 ? PI_2F : (n1 ? PI_F : 0.0f);
        const float sal0 = (p0 == n0) ? al0 : -al0;
        const float sal1 = (p1 == n1) ? al1 : -al1;
        float th0 = base0 + sal0;
        float th1 = base1 + sal1;

        // exact reference clamp semantics: clip(theta, acos(1-eps), pi-acos(1-eps))
        th0 = fminf(fmaxf(th0, THMIN), THMAX);
        th1 = fminf(fmaxf(th1, THMIN), THMAX);

        const float s0 = ftanh(tk0);
        const float s1 = ftanh(tk1);
        sum0 = fmaf(s0, th0, sum0);
        sum1 = fmaf(s1, th1, sum1);

        // carry: this edge's roll is next edge's diff
        dxv = rxv; dyv = ryv;
    }

    const int base = row * MSIZE + col0;
    out[base]       = fminf(fmaxf(sum0 * INV2PI, 0.0f), 1.0f);
    out[base + 128] = fminf(fmaxf(sum1 * INV2PI, 0.0f), 1.0f);
}

extern "C" void kernel_launch(void* const* d_in, const int* in_sizes, int n_in,
                              void* d_out, int out_size) {
    const float* contour = (const float*)d_in[0];
    float* out = (float*)d_out;
    contour_mask_kernel<<<MSIZE * 2, 128>>>(contour, out);
}

// round 6
// speedup vs baseline: 1.2393x; 1.1813x over previous
#include <cuda_runtime.h>
#include <cuda_bf16.h>

// Contour_to_mask: winding-number mask, 512x512 px, 128 contour points.
// Reference: sum_n tanh(K*cross_n) * acos(clip(cos_n,-1+eps,1-eps)) / 2pi, clipped [0,1].
// theta = acos(dot/(|d||r|)) = atan2(|cross|, dot); clamp maps exactly to
// theta in [acos(1-eps), pi-acos(1-eps)].
// Algebra: cross_j = w_j + py*ex_j - px*ey_j,  dot_j = d_j + px(px-sx_j) + py(py-sy_j)
// with per-edge constants; px is block-constant so it is folded into smem once per
// block -> per-iteration front-end is 3 packed ops, no carried state.
// Everything scaled by K (ratio & signs invariant; tanh input comes out directly).

#define MSIZE 512
#define NPTS  128
#define KCONST 100000.0f
#define INV2PI 0.15915494309189535f
#define PI_2F  1.57079632679489662f
#define THMIN  0.0044721364f            /* acos(1 - 1e-5) */
#define THMAX  3.1371205172f            /* pi - acos(1 - 1e-5) */

typedef unsigned long long u64;

__device__ __forceinline__ u64 pk2(float lo, float hi) {
    u64 r; asm("mov.b64 %0,{%1,%2};" : "=l"(r) : "f"(lo), "f"(hi)); return r;
}
__device__ __forceinline__ void upk2(u64 v, float& lo, float& hi) {
    asm("mov.b64 {%0,%1},%2;" : "=f"(lo), "=f"(hi) : "l"(v));
}
__device__ __forceinline__ u64 mul2(u64 a, u64 b) {
    u64 r; asm("mul.rn.f32x2 %0,%1,%2;" : "=l"(r) : "l"(a), "l"(b)); return r;
}
__device__ __forceinline__ u64 add2(u64 a, u64 b) {
    u64 r; asm("add.rn.f32x2 %0,%1,%2;" : "=l"(r) : "l"(a), "l"(b)); return r;
}
__device__ __forceinline__ u64 fma2(u64 a, u64 b, u64 c) {
    u64 r; asm("fma.rn.f32x2 %0,%1,%2,%3;" : "=l"(r) : "l"(a), "l"(b), "l"(c)); return r;
}
__device__ __forceinline__ float ftanh(float x) {
    float r; asm("tanh.approx.f32 %0,%1;" : "=f"(r) : "f"(x)); return r;
}
__device__ __forceinline__ float frcp(float x) {
    float r; asm("rcp.approx.f32 %0,%1;" : "=f"(r) : "f"(x)); return r;
}
// +-1.0f carrying the sign of x: one LOP3
__device__ __forceinline__ float sgn1(float x) {
    return __int_as_float(0x3f800000 | (__float_as_int(x) & 0x80000000));
}

__global__ void __launch_bounds__(128)
contour_mask_kernel(const float* __restrict__ contour, float* __restrict__ out) {
    // per-edge, per-block constants, duplicated into lane pairs:
    // s[2j]   = (tK, tK, exK, exK)   tK = K*(w - px*ey), exK = K*ex
    // s[2j+1] = (UK, UK, -sy, -sy)   UK = K*(d + px*(px-sx))
    __shared__ float4 s[2 * NPTS];
    const int t = threadIdx.x;
    const int row = blockIdx.x >> 1;
    const float px = (float)row * (1.0f / (float)MSIZE);

    if (t < NPTS) {
        const float2 c0 = reinterpret_cast<const float2*>(contour)[t];
        const float2 c1 = reinterpret_cast<const float2*>(contour)[(t + 1) & (NPTS - 1)];
        const float w  = fmaf(c0.y, c1.x, -(c0.x * c1.y));  // cy0*cx1 - cx0*cy1
        const float ex = c0.x - c1.x;
        const float ey = c0.y - c1.y;
        const float d  = fmaf(c0.x, c1.x, c0.y * c1.y);
        const float sx = c0.x + c1.x;
        const float sy = c0.y + c1.y;
        const float tK  = KCONST * fmaf(-px, ey, w);
        const float exK = KCONST * ex;
        const float UK  = KCONST * fmaf(px, px - sx, d);
        s[2 * t]     = make_float4(tK, tK, exK, exK);
        s[2 * t + 1] = make_float4(UK, UK, -sy, -sy);
    }
    __syncthreads();

    const int col0 = ((blockIdx.x & 1) << 8) + t;
    const float py0 = (float)col0         * (1.0f / (float)MSIZE);
    const float py1 = (float)(col0 + 128) * (1.0f / (float)MSIZE);
    const u64 pyv  = pk2(py0, py1);
    const u64 Kpyv = pk2(KCONST * py0, KCONST * py1);

    // atan poly, A&S 4.4.47 (|err| <= 1e-5 rad on [0,1]): atan(r) ~ r*P(r^2)
    const u64 A9 = pk2( 0.0208351f,  0.0208351f);
    const u64 A7 = pk2(-0.0851330f, -0.0851330f);
    const u64 A5 = pk2( 0.1801410f,  0.1801410f);
    const u64 A3 = pk2(-0.3302995f, -0.3302995f);
    const u64 A1 = pk2( 0.9998660f,  0.9998660f);

    const u64* sv = reinterpret_cast<const u64*>(s);

    float sum0 = 0.0f, sum1 = 0.0f;

#pragma unroll 8
    for (int j = 0; j < NPTS; ++j) {
        const u64 tKv  = sv[4 * j];
        const u64 exKv = sv[4 * j + 1];
        const u64 UKv  = sv[4 * j + 2];
        const u64 nsyv = sv[4 * j + 3];

        const u64 crv = fma2(pyv, exKv, tKv);            // K*cross
        const u64 pys = add2(pyv, nsyv);                 // py - sy
        const u64 dtv = fma2(Kpyv, pys, UKv);            // K*dot

        float cr0, cr1, c0, c1;
        upk2(crv, cr0, cr1);
        upk2(dtv, c0, c1);

        const float a0 = fabsf(cr0), a1 = fabsf(cr1);
        const float b0 = fabsf(c0),  b1 = fabsf(c1);
        const float M0 = fmaxf(a0, b0), M1 = fmaxf(a1, b1);
        const float m0 = fminf(a0, b0), m1 = fminf(a1, b1);
        const float r0 = m0 * frcp(M0);
        const float r1 = m1 * frcp(M1);

        // packed odd poly: al = atan(r), r in [0,1]
        const u64 rv  = pk2(r0, r1);
        const u64 r2v = mul2(rv, rv);
        u64 pv = fma2(A9, r2v, A7);
        pv = fma2(pv, r2v, A5);
        pv = fma2(pv, r2v, A3);
        pv = fma2(pv, r2v, A1);
        const u64 av = mul2(pv, rv);
        float al0, al1;
        upk2(av, al0, al1);

        // v = atan(|dot|/|cross|) in [0,pi/2];  theta = pi/2 - sign(dot)*v
        const float h0 = PI_2F - al0;
        const float h1 = PI_2F - al1;
        const float v0 = (b0 > a0) ? h0 : al0;
        const float v1 = (b1 > a1) ? h1 : al1;
        float th0 = fmaf(sgn1(c0), -v0, PI_2F);
        float th1 = fmaf(sgn1(c1), -v1, PI_2F);

        // exact reference clamp: theta in [acos(1-eps), pi-acos(1-eps)]
        th0 = fminf(fmaxf(th0, THMIN), THMAX);
        th1 = fminf(fmaxf(th1, THMIN), THMAX);

        sum0 = fmaf(ftanh(cr0), th0, sum0);              // crK IS K*cross
        sum1 = fmaf(ftanh(cr1), th1, sum1);
    }

    const int base = row * MSIZE + col0;
    out[base]       = fminf(fmaxf(sum0 * INV2PI, 0.0f), 1.0f);
    out[base + 128] = fminf(fmaxf(sum1 * INV2PI, 0.0f), 1.0f);
}

extern "C" void kernel_launch(void* const* d_in, const int* in_sizes, int n_in,
                              void* d_out, int out_size) {
    const float* contour = (const float*)d_in[0];
    float* out = (float*)d_out;
    contour_mask_kernel<<<MSIZE * 2, 128>>>(contour, out);
}